// round 10
// baseline (speedup 1.0000x reference)
#include <cuda_runtime.h>
#include <cuda_bf16.h>
#include <cstdint>

#define BATCH 16
#define NTOK  2048
#define DDIM  256
#define SHIFTC 40.0f

// ---------------- scratch (device globals; no allocation allowed) ----------
__device__ __nv_bfloat16 g_Qhi[(size_t)BATCH * NTOK * DDIM];
__device__ __nv_bfloat16 g_Qlo[(size_t)BATCH * NTOK * DDIM];
__device__ __nv_bfloat16 g_Khi[(size_t)BATCH * NTOK * DDIM];
__device__ __nv_bfloat16 g_Klo[(size_t)BATCH * NTOK * DDIM];
__device__ float g_S[(size_t)BATCH * NTOK * NTOK];          // 268 MB
__device__ float g_Zpart[8 * BATCH * NTOK];                 // per-kc row sumexp
__device__ float g_rZ[BATCH * NTOK];
__device__ float g_cpart[8 * BATCH * NTOK];
__device__ float g_ypart[16 * BATCH * DDIM];

// ---------------- helpers ---------------------------------------------------
__device__ __forceinline__ uint32_t smem_u32(const void* p) {
    uint32_t a;
    asm("{ .reg .u64 t; cvta.to.shared.u64 t, %1; cvt.u32.u64 %0, t; }"
        : "=r"(a) : "l"(p));
    return a;
}
#define SW128(b) ((b) ^ (((b) >> 3) & 0x70))

#define CP_ASYNC16(dst, src) \
    asm volatile("cp.async.cg.shared.global [%0], [%1], 16;" :: "r"(dst), "l"(src))
#define CP_COMMIT() asm volatile("cp.async.commit_group;" ::: "memory")
#define CP_WAIT(n)  asm volatile("cp.async.wait_group %0;" :: "n"(n) : "memory")

__device__ __forceinline__ void ldsm_x4(uint32_t* r, uint32_t addr) {
    asm volatile("ldmatrix.sync.aligned.m8n8.x4.shared.b16 {%0,%1,%2,%3}, [%4];"
                 : "=r"(r[0]), "=r"(r[1]), "=r"(r[2]), "=r"(r[3]) : "r"(addr));
}
__device__ __forceinline__ void mma16816(float* c, const uint32_t* a, const uint32_t* b) {
    asm volatile(
        "mma.sync.aligned.m16n8k16.row.col.f32.bf16.bf16.f32 "
        "{%0,%1,%2,%3}, {%4,%5,%6,%7}, {%8,%9}, {%0,%1,%2,%3};"
        : "+f"(c[0]), "+f"(c[1]), "+f"(c[2]), "+f"(c[3])
        : "r"(a[0]), "r"(a[1]), "r"(a[2]), "r"(a[3]), "r"(b[0]), "r"(b[1]));
}

// ---------------------------------------------------------------------------
// Kernel 1: Q/K projections (SIMT fp32), epilogue emits bf16 hi/lo split.
// ---------------------------------------------------------------------------
__global__ __launch_bounds__(256) void proj_kernel(
    const float* __restrict__ X,
    const float* __restrict__ W1, const float* __restrict__ b1,
    const float* __restrict__ W2, const float* __restrict__ b2)
{
    const float* W  = (blockIdx.z == 0) ? W1 : W2;
    const float* bv = (blockIdx.z == 0) ? b1 : b2;
    __nv_bfloat16* Hi = (blockIdx.z == 0) ? g_Qhi : g_Khi;
    __nv_bfloat16* Lo = (blockIdx.z == 0) ? g_Qlo : g_Klo;

    __shared__ float As[16][132];
    __shared__ float Bs[16][132];

    const int tid = threadIdx.x;
    const int tx = tid & 15;
    const int ty = tid >> 4;
    const int row0 = blockIdx.x * 128;
    const int col0 = blockIdx.y * 128;

    float acc[8][8];
    #pragma unroll
    for (int i = 0; i < 8; i++)
        #pragma unroll
        for (int j = 0; j < 8; j++) acc[i][j] = 0.f;

    for (int k0 = 0; k0 < 256; k0 += 16) {
        #pragma unroll
        for (int l = 0; l < 2; l++) {
            int idx = tid + l * 256;
            int r = idx >> 2, c4 = idx & 3;
            float4 v = *(const float4*)(X + (size_t)(row0 + r) * 256 + k0 + c4 * 4);
            As[c4 * 4 + 0][r] = v.x;
            As[c4 * 4 + 1][r] = v.y;
            As[c4 * 4 + 2][r] = v.z;
            As[c4 * 4 + 3][r] = v.w;
        }
        #pragma unroll
        for (int l = 0; l < 2; l++) {
            int idx = tid + l * 256;
            int r = idx >> 5, c4 = idx & 31;
            *(float4*)&Bs[r][c4 * 4] =
                *(const float4*)(W + (size_t)(k0 + r) * 256 + col0 + c4 * 4);
        }
        __syncthreads();

        #pragma unroll
        for (int kk = 0; kk < 16; kk++) {
            float a[8], b[8];
            *(float4*)&a[0] = *(const float4*)&As[kk][ty * 8];
            *(float4*)&a[4] = *(const float4*)&As[kk][ty * 8 + 4];
            *(float4*)&b[0] = *(const float4*)&Bs[kk][tx * 8];
            *(float4*)&b[4] = *(const float4*)&Bs[kk][tx * 8 + 4];
            #pragma unroll
            for (int i = 0; i < 8; i++)
                #pragma unroll
                for (int j = 0; j < 8; j++)
                    acc[i][j] += a[i] * b[j];
        }
        __syncthreads();
    }

    float bj[8];
    *(float4*)&bj[0] = *(const float4*)(bv + col0 + tx * 8);
    *(float4*)&bj[4] = *(const float4*)(bv + col0 + tx * 8 + 4);
    #pragma unroll
    for (int i = 0; i < 8; i++) {
        size_t off = (size_t)(row0 + ty * 8 + i) * 256 + col0 + tx * 8;
        union { __nv_bfloat16 b[8]; uint4 v; } uh, ul;
        #pragma unroll
        for (int j = 0; j < 8; j++) {
            float v = acc[i][j] + bj[j];
            __nv_bfloat16 h = __float2bfloat16(v);
            uh.b[j] = h;
            ul.b[j] = __float2bfloat16(v - __bfloat162float(h));
        }
        *(uint4*)(Hi + off) = uh.v;
        *(uint4*)(Lo + off) = ul.v;
    }
}

// ---------------------------------------------------------------------------
// Kernel 2: S = Q K^T via mma.sync bf16 2-term split (3 MMAs per product).
// CTA tile 128(M) x 256(N); 8 warps, warp tile 64x64 (2M x 4N).
// K chunks of 64, double-buffered cp.async, SW128 smem.
// Epilogue: write S + per-row sum(exp(s-C)) partial -> g_Zpart.
// SMEM layout: [0,2048) zbuf; [2048, +2*98304) buffers:
//   per stage: Ahi@0 (16KB) Alo@16K Bhi@32K (32KB) Blo@64K
// ---------------------------------------------------------------------------
#define SC_STAGE 98304
#define SC_SMEM  (2048 + 2 * SC_STAGE)

__global__ __launch_bounds__(256, 1) void score_mma_kernel()
{
    extern __shared__ char smem[];
    float* zbuf = (float*)smem;                      // [4][128]
    const uint32_t bufs = smem_u32(smem) + 2048;

    const int tid  = threadIdx.x;
    const int wid  = tid >> 5;
    const int lane = tid & 31;

    const int q0  = blockIdx.x * 128;
    const int kc0 = blockIdx.y * 256;
    const int bb  = blockIdx.z;

    const __nv_bfloat16* Ah = g_Qhi + ((size_t)bb * NTOK + q0) * DDIM;
    const __nv_bfloat16* Al = g_Qlo + ((size_t)bb * NTOK + q0) * DDIM;
    const __nv_bfloat16* Bh = g_Khi + ((size_t)bb * NTOK + kc0) * DDIM;
    const __nv_bfloat16* Bl = g_Klo + ((size_t)bb * NTOK + kc0) * DDIM;

    auto load_chunk = [&](int c, int buf) {
        const uint32_t bufb = bufs + buf * SC_STAGE;
        const int ko = c * 64;
        #pragma unroll
        for (int l = 0; l < 4; l++) {                  // A: 128 rows x 8 x 16B
            int i = tid + l * 256;
            int row = i >> 3, c16 = i & 7;
            uint32_t so = SW128(row * 128 + c16 * 16);
            const size_t go = (size_t)row * 256 + ko + c16 * 8;
            CP_ASYNC16(bufb + so,         Ah + go);
            CP_ASYNC16(bufb + 16384 + so, Al + go);
        }
        #pragma unroll
        for (int l = 0; l < 8; l++) {                  // B: 256 rows x 8 x 16B
            int i = tid + l * 256;
            int row = i >> 3, c16 = i & 7;
            uint32_t so = SW128(row * 128 + c16 * 16);
            const size_t go = (size_t)row * 256 + ko + c16 * 8;
            CP_ASYNC16(bufb + 32768 + so, Bh + go);
            CP_ASYNC16(bufb + 65536 + so, Bl + go);
        }
        CP_COMMIT();
    };

    float acc[4][8][4];
    #pragma unroll
    for (int i = 0; i < 4; i++)
        #pragma unroll
        for (int j = 0; j < 8; j++)
            #pragma unroll
            for (int k = 0; k < 4; k++) acc[i][j][k] = 0.f;

    const int warpM = wid & 1;          // 0..1 -> 64 rows
    const int warpN = wid >> 1;         // 0..3 -> 64 cols

    // ldmatrix per-lane addressing (byte offsets before swizzle)
    const int aRow = warpM * 64 + (lane & 15);            // + i*16
    const int aColB = (lane >> 4) << 4;                   // k-half 16B
    const int bRow = warpN * 64 + (lane & 7) + ((lane >> 4) << 3);  // + j*16
    const int bColB = ((lane >> 3) & 1) << 4;

    load_chunk(0, 0);

    for (int c = 0; c < 4; c++) {
        if (c < 3) { load_chunk(c + 1, (c + 1) & 1); CP_WAIT(1); }
        else       { CP_WAIT(0); }
        __syncthreads();

        const uint32_t base = bufs + (c & 1) * SC_STAGE;
        #pragma unroll
        for (int kk = 0; kk < 4; kk++) {
            uint32_t ah[4][4], al[4][4];
            #pragma unroll
            for (int i = 0; i < 4; i++) {
                uint32_t off = (uint32_t)(aRow + i * 16) * 128 + kk * 32 + aColB;
                uint32_t sw = SW128(off);
                ldsm_x4(ah[i], base + sw);
                ldsm_x4(al[i], base + 16384 + sw);
            }
            #pragma unroll
            for (int j = 0; j < 4; j++) {
                uint32_t off = (uint32_t)(bRow + j * 16) * 128 + kk * 32 + bColB;
                uint32_t sw = SW128(off);
                uint32_t bh[4], bl[4];
                ldsm_x4(bh, base + 32768 + sw);
                ldsm_x4(bl, base + 65536 + sw);
                #pragma unroll
                for (int i = 0; i < 4; i++) {
                    mma16816(acc[i][2 * j],     ah[i], &bh[0]);
                    mma16816(acc[i][2 * j + 1], ah[i], &bh[2]);
                    mma16816(acc[i][2 * j],     ah[i], &bl[0]);
                    mma16816(acc[i][2 * j + 1], ah[i], &bl[2]);
                    mma16816(acc[i][2 * j],     al[i], &bh[0]);
                    mma16816(acc[i][2 * j + 1], al[i], &bh[2]);
                }
            }
        }
        __syncthreads();
    }

    // ---- epilogue: store S, accumulate row sum(exp(s - C)) ------------------
    float* S = g_S + (size_t)bb * NTOK * NTOK;
    #pragma unroll
    for (int i = 0; i < 4; i++) {
        const int r0 = q0 + warpM * 64 + i * 16 + (lane >> 2);
        #pragma unroll
        for (int jj = 0; jj < 8; jj++) {
            const int col = kc0 + warpN * 64 + jj * 8 + (lane & 3) * 2;
            float2 lo = make_float2(acc[i][jj][0], acc[i][jj][1]);
            float2 hi = make_float2(acc[i][jj][2], acc[i][jj][3]);
            *(float2*)(S + (size_t)r0 * NTOK + col)       = lo;
            *(float2*)(S + (size_t)(r0 + 8) * NTOK + col) = hi;
        }
    }

    #pragma unroll
    for (int i = 0; i < 4; i++) {
        float s0 = 0.f, s1 = 0.f;
        #pragma unroll
        for (int jj = 0; jj < 8; jj++) {
            s0 += __expf(acc[i][jj][0] - SHIFTC) + __expf(acc[i][jj][1] - SHIFTC);
            s1 += __expf(acc[i][jj][2] - SHIFTC) + __expf(acc[i][jj][3] - SHIFTC);
        }
        s0 += __shfl_xor_sync(0xffffffffu, s0, 1);
        s0 += __shfl_xor_sync(0xffffffffu, s0, 2);
        s1 += __shfl_xor_sync(0xffffffffu, s1, 1);
        s1 += __shfl_xor_sync(0xffffffffu, s1, 2);
        if ((lane & 3) == 0) {
            int r = warpM * 64 + i * 16 + (lane >> 2);
            zbuf[warpN * 128 + r]     = s0;
            zbuf[warpN * 128 + r + 8] = s1;
        }
    }
    __syncthreads();
    if (tid < 128) {
        float t = zbuf[tid] + zbuf[128 + tid] + zbuf[256 + tid] + zbuf[384 + tid];
        g_Zpart[(blockIdx.y * BATCH + bb) * NTOK + q0 + tid] = t;
    }
}

// ---------------------------------------------------------------------------
// Kernel 3: rZ = 1 / sum_kc Zpart
// ---------------------------------------------------------------------------
__global__ __launch_bounds__(256) void zsum_kernel()
{
    const int i = blockIdx.x * 256 + threadIdx.x;     // 0..32767
    float t = 0.f;
    #pragma unroll
    for (int p = 0; p < 8; p++) t += g_Zpart[p * (BATCH * NTOK) + i];
    g_rZ[i] = 1.0f / t;
}

// ---------------------------------------------------------------------------
// Kernel 4: column-sum partials: c_k partial = sum_q exp(S_qk - C) * rZ_q
// grid (8 kchunks, 16 batch, 8 qchunks)
// ---------------------------------------------------------------------------
__global__ __launch_bounds__(256) void colsum_kernel()
{
    const int bb = blockIdx.y;
    const int qc = blockIdx.z;
    const int k  = blockIdx.x * 256 + threadIdx.x;
    const int qbase = qc * 256;

    __shared__ float shz[256];
    shz[threadIdx.x] = g_rZ[bb * NTOK + qbase + threadIdx.x];
    __syncthreads();

    const float* S = g_S + (size_t)bb * NTOK * NTOK + (size_t)qbase * NTOK + k;
    float acc = 0.f;
    for (int q = 0; q < 256; q += 16) {
        float sv[16];
        #pragma unroll
        for (int u = 0; u < 16; u++) sv[u] = S[(size_t)(q + u) * NTOK];
        #pragma unroll
        for (int u = 0; u < 16; u++)
            acc += __expf(sv[u] - SHIFTC) * shz[q + u];
    }
    g_cpart[(qc * BATCH + bb) * NTOK + k] = acc;
}

// ---------------------------------------------------------------------------
// Kernel 5: ypart[ks][b][d] = sum over 128 k of c[b,k] * x[b,k,d]
// ---------------------------------------------------------------------------
__global__ __launch_bounds__(256) void ypart_kernel(const float* __restrict__ x)
{
    const int bb = blockIdx.y;
    const int ks = blockIdx.x;
    const int k0 = ks * 128;

    __shared__ float sc[128];
    if (threadIdx.x < 128) {
        float s = 0.f;
        #pragma unroll
        for (int p = 0; p < 8; p++)
            s += g_cpart[(p * BATCH + bb) * NTOK + k0 + threadIdx.x];
        sc[threadIdx.x] = s;
    }
    __syncthreads();

    const float* X = x + ((size_t)bb * NTOK + k0) * DDIM + threadIdx.x;
    float acc = 0.f;
    #pragma unroll 8
    for (int kk = 0; kk < 128; kk++)
        acc += sc[kk] * X[(size_t)kk * DDIM];
    g_ypart[(ks * BATCH + bb) * DDIM + threadIdx.x] = acc;
}

// ---------------------------------------------------------------------------
// Kernel 6: out[b,a] = y[b,:] @ W3[:,a] + 2048*b3[a]
// ---------------------------------------------------------------------------
__global__ __launch_bounds__(256) void out_kernel(
    const float* __restrict__ W3, const float* __restrict__ b3,
    float* __restrict__ out)
{
    const int bb = blockIdx.x;
    const int a  = threadIdx.x;

    __shared__ float y[DDIM];
    float t = 0.f;
    #pragma unroll
    for (int p = 0; p < 16; p++) t += g_ypart[(p * BATCH + bb) * DDIM + a];
    y[a] = t;
    __syncthreads();

    float acc = 2048.0f * b3[a];
    #pragma unroll 8
    for (int d = 0; d < DDIM; d++)
        acc += y[d] * W3[(size_t)d * DDIM + a];
    out[bb * DDIM + a] = acc;
}

// ---------------------------------------------------------------------------
extern "C" void kernel_launch(void* const* d_in, const int* in_sizes, int n_in,
                              void* d_out, int out_size)
{
    const float* x  = (const float*)d_in[0];
    const float* W1 = (const float*)d_in[1];
    const float* b1 = (const float*)d_in[2];
    const float* W2 = (const float*)d_in[3];
    const float* b2 = (const float*)d_in[4];
    const float* W3 = (const float*)d_in[5];
    const float* b3 = (const float*)d_in[6];
    float* out = (float*)d_out;

    cudaFuncSetAttribute(score_mma_kernel,
                         cudaFuncAttributeMaxDynamicSharedMemorySize, SC_SMEM);

    proj_kernel<<<dim3(256, 2, 2), 256>>>(x, W1, b1, W2, b2);
    score_mma_kernel<<<dim3(16, 8, 16), 256, SC_SMEM>>>();
    zsum_kernel<<<128, 256>>>();
    colsum_kernel<<<dim3(8, 16, 8), 256>>>();
    ypart_kernel<<<dim3(16, 16), 256>>>(x);
    out_kernel<<<16, 256>>>(W3, b3, out);
}

// round 11
// speedup vs baseline: 1.0033x; 1.0033x over previous
#include <cuda_runtime.h>
#include <cuda_bf16.h>
#include <cstdint>

#define BATCH 16
#define NTOK  2048
#define DDIM  256
#define SHIFTC 40.0f

// ---------------- scratch (device globals; no allocation allowed) ----------
__device__ __nv_bfloat16 g_Qhi[(size_t)BATCH * NTOK * DDIM];
__device__ __nv_bfloat16 g_Qlo[(size_t)BATCH * NTOK * DDIM];
__device__ __nv_bfloat16 g_Khi[(size_t)BATCH * NTOK * DDIM];
__device__ __nv_bfloat16 g_Klo[(size_t)BATCH * NTOK * DDIM];
__device__ float g_S[(size_t)BATCH * NTOK * NTOK];          // 268 MB
__device__ float g_Zpart[8 * BATCH * NTOK];                 // per-kc row sumexp
__device__ float g_rZ[BATCH * NTOK];
__device__ float g_cpart[8 * BATCH * NTOK];
__device__ float g_ypart[16 * BATCH * DDIM];

// ---------------- helpers ---------------------------------------------------
__device__ __forceinline__ uint32_t smem_u32(const void* p) {
    uint32_t a;
    asm("{ .reg .u64 t; cvta.to.shared.u64 t, %1; cvt.u32.u64 %0, t; }"
        : "=r"(a) : "l"(p));
    return a;
}
#define SW128(b) ((b) ^ (((b) >> 3) & 0x70))

#define CP_ASYNC16(dst, src) \
    asm volatile("cp.async.cg.shared.global [%0], [%1], 16;" :: "r"(dst), "l"(src))
#define CP_COMMIT() asm volatile("cp.async.commit_group;" ::: "memory")
#define CP_WAIT(n)  asm volatile("cp.async.wait_group %0;" :: "n"(n) : "memory")

__device__ __forceinline__ void ldsm_x4(uint32_t* r, uint32_t addr) {
    asm volatile("ldmatrix.sync.aligned.m8n8.x4.shared.b16 {%0,%1,%2,%3}, [%4];"
                 : "=r"(r[0]), "=r"(r[1]), "=r"(r[2]), "=r"(r[3]) : "r"(addr));
}
__device__ __forceinline__ void mma16816(float* c, const uint32_t* a, const uint32_t* b) {
    asm volatile(
        "mma.sync.aligned.m16n8k16.row.col.f32.bf16.bf16.f32 "
        "{%0,%1,%2,%3}, {%4,%5,%6,%7}, {%8,%9}, {%0,%1,%2,%3};"
        : "+f"(c[0]), "+f"(c[1]), "+f"(c[2]), "+f"(c[3])
        : "r"(a[0]), "r"(a[1]), "r"(a[2]), "r"(a[3]), "r"(b[0]), "r"(b[1]));
}

// ---------------------------------------------------------------------------
// Kernel 1: Q/K projections (SIMT fp32), epilogue emits bf16 hi/lo split.
// ---------------------------------------------------------------------------
__global__ __launch_bounds__(256) void proj_kernel(
    const float* __restrict__ X,
    const float* __restrict__ W1, const float* __restrict__ b1,
    const float* __restrict__ W2, const float* __restrict__ b2)
{
    const float* W  = (blockIdx.z == 0) ? W1 : W2;
    const float* bv = (blockIdx.z == 0) ? b1 : b2;
    __nv_bfloat16* Hi = (blockIdx.z == 0) ? g_Qhi : g_Khi;
    __nv_bfloat16* Lo = (blockIdx.z == 0) ? g_Qlo : g_Klo;

    __shared__ float As[16][132];
    __shared__ float Bs[16][132];

    const int tid = threadIdx.x;
    const int tx = tid & 15;
    const int ty = tid >> 4;
    const int row0 = blockIdx.x * 128;
    const int col0 = blockIdx.y * 128;

    float acc[8][8];
    #pragma unroll
    for (int i = 0; i < 8; i++)
        #pragma unroll
        for (int j = 0; j < 8; j++) acc[i][j] = 0.f;

    for (int k0 = 0; k0 < 256; k0 += 16) {
        #pragma unroll
        for (int l = 0; l < 2; l++) {
            int idx = tid + l * 256;
            int r = idx >> 2, c4 = idx & 3;
            float4 v = *(const float4*)(X + (size_t)(row0 + r) * 256 + k0 + c4 * 4);
            As[c4 * 4 + 0][r] = v.x;
            As[c4 * 4 + 1][r] = v.y;
            As[c4 * 4 + 2][r] = v.z;
            As[c4 * 4 + 3][r] = v.w;
        }
        #pragma unroll
        for (int l = 0; l < 2; l++) {
            int idx = tid + l * 256;
            int r = idx >> 5, c4 = idx & 31;
            *(float4*)&Bs[r][c4 * 4] =
                *(const float4*)(W + (size_t)(k0 + r) * 256 + col0 + c4 * 4);
        }
        __syncthreads();

        #pragma unroll
        for (int kk = 0; kk < 16; kk++) {
            float a[8], b[8];
            *(float4*)&a[0] = *(const float4*)&As[kk][ty * 8];
            *(float4*)&a[4] = *(const float4*)&As[kk][ty * 8 + 4];
            *(float4*)&b[0] = *(const float4*)&Bs[kk][tx * 8];
            *(float4*)&b[4] = *(const float4*)&Bs[kk][tx * 8 + 4];
            #pragma unroll
            for (int i = 0; i < 8; i++)
                #pragma unroll
                for (int j = 0; j < 8; j++)
                    acc[i][j] += a[i] * b[j];
        }
        __syncthreads();
    }

    float bj[8];
    *(float4*)&bj[0] = *(const float4*)(bv + col0 + tx * 8);
    *(float4*)&bj[4] = *(const float4*)(bv + col0 + tx * 8 + 4);
    #pragma unroll
    for (int i = 0; i < 8; i++) {
        size_t off = (size_t)(row0 + ty * 8 + i) * 256 + col0 + tx * 8;
        union { __nv_bfloat16 b[8]; uint4 v; } uh, ul;
        #pragma unroll
        for (int j = 0; j < 8; j++) {
            float v = acc[i][j] + bj[j];
            __nv_bfloat16 h = __float2bfloat16(v);
            uh.b[j] = h;
            ul.b[j] = __float2bfloat16(v - __bfloat162float(h));
        }
        *(uint4*)(Hi + off) = uh.v;
        *(uint4*)(Lo + off) = ul.v;
    }
}

// ---------------------------------------------------------------------------
// Kernel 2: S = Q K^T via mma.sync bf16 2-term split (3 MMAs per product).
// CTA tile 128(M) x 256(N); 8 warps, warp tile 64x64 (2M x 4N).
// K chunks of 64, double-buffered cp.async, SW128 smem.
// Epilogue: write S + per-row sum(exp(s-C)) partial -> g_Zpart.
// SMEM layout: [0,2048) zbuf; [2048, +2*98304) buffers:
//   per stage: Ahi@0 (16KB) Alo@16K Bhi@32K (32KB) Blo@64K
// ---------------------------------------------------------------------------
#define SC_STAGE 98304
#define SC_SMEM  (2048 + 2 * SC_STAGE)

__global__ __launch_bounds__(256, 1) void score_mma_kernel()
{
    extern __shared__ char smem[];
    float* zbuf = (float*)smem;                      // [4][128]
    const uint32_t bufs = smem_u32(smem) + 2048;

    const int tid  = threadIdx.x;
    const int wid  = tid >> 5;
    const int lane = tid & 31;

    const int q0  = blockIdx.x * 128;
    const int kc0 = blockIdx.y * 256;
    const int bb  = blockIdx.z;

    const __nv_bfloat16* Ah = g_Qhi + ((size_t)bb * NTOK + q0) * DDIM;
    const __nv_bfloat16* Al = g_Qlo + ((size_t)bb * NTOK + q0) * DDIM;
    const __nv_bfloat16* Bh = g_Khi + ((size_t)bb * NTOK + kc0) * DDIM;
    const __nv_bfloat16* Bl = g_Klo + ((size_t)bb * NTOK + kc0) * DDIM;

    auto load_chunk = [&](int c, int buf) {
        const uint32_t bufb = bufs + buf * SC_STAGE;
        const int ko = c * 64;
        #pragma unroll
        for (int l = 0; l < 4; l++) {                  // A: 128 rows x 8 x 16B
            int i = tid + l * 256;
            int row = i >> 3, c16 = i & 7;
            uint32_t so = SW128(row * 128 + c16 * 16);
            const size_t go = (size_t)row * 256 + ko + c16 * 8;
            CP_ASYNC16(bufb + so,         Ah + go);
            CP_ASYNC16(bufb + 16384 + so, Al + go);
        }
        #pragma unroll
        for (int l = 0; l < 8; l++) {                  // B: 256 rows x 8 x 16B
            int i = tid + l * 256;
            int row = i >> 3, c16 = i & 7;
            uint32_t so = SW128(row * 128 + c16 * 16);
            const size_t go = (size_t)row * 256 + ko + c16 * 8;
            CP_ASYNC16(bufb + 32768 + so, Bh + go);
            CP_ASYNC16(bufb + 65536 + so, Bl + go);
        }
        CP_COMMIT();
    };

    float acc[4][8][4];
    #pragma unroll
    for (int i = 0; i < 4; i++)
        #pragma unroll
        for (int j = 0; j < 8; j++)
            #pragma unroll
            for (int k = 0; k < 4; k++) acc[i][j][k] = 0.f;

    const int warpM = wid & 1;          // 0..1 -> 64 rows
    const int warpN = wid >> 1;         // 0..3 -> 64 cols

    // ldmatrix per-lane addressing (byte offsets before swizzle)
    const int aRow = warpM * 64 + (lane & 15);            // + i*16
    const int aColB = (lane >> 4) << 4;                   // k-half 16B
    const int bRow = warpN * 64 + (lane & 7) + ((lane >> 4) << 3);  // + j*16
    const int bColB = ((lane >> 3) & 1) << 4;

    load_chunk(0, 0);

    for (int c = 0; c < 4; c++) {
        if (c < 3) { load_chunk(c + 1, (c + 1) & 1); CP_WAIT(1); }
        else       { CP_WAIT(0); }
        __syncthreads();

        const uint32_t base = bufs + (c & 1) * SC_STAGE;
        #pragma unroll
        for (int kk = 0; kk < 4; kk++) {
            uint32_t ah[4][4], al[4][4];
            #pragma unroll
            for (int i = 0; i < 4; i++) {
                uint32_t off = (uint32_t)(aRow + i * 16) * 128 + kk * 32 + aColB;
                uint32_t sw = SW128(off);
                ldsm_x4(ah[i], base + sw);
                ldsm_x4(al[i], base + 16384 + sw);
            }
            #pragma unroll
            for (int j = 0; j < 4; j++) {
                uint32_t off = (uint32_t)(bRow + j * 16) * 128 + kk * 32 + bColB;
                uint32_t sw = SW128(off);
                uint32_t bh[4], bl[4];
                ldsm_x4(bh, base + 32768 + sw);
                ldsm_x4(bl, base + 65536 + sw);
                #pragma unroll
                for (int i = 0; i < 4; i++) {
                    mma16816(acc[i][2 * j],     ah[i], &bh[0]);
                    mma16816(acc[i][2 * j + 1], ah[i], &bh[2]);
                    mma16816(acc[i][2 * j],     ah[i], &bl[0]);
                    mma16816(acc[i][2 * j + 1], ah[i], &bl[2]);
                    mma16816(acc[i][2 * j],     al[i], &bh[0]);
                    mma16816(acc[i][2 * j + 1], al[i], &bh[2]);
                }
            }
        }
        __syncthreads();
    }

    // ---- epilogue: store S, accumulate row sum(exp(s - C)) ------------------
    float* S = g_S + (size_t)bb * NTOK * NTOK;
    #pragma unroll
    for (int i = 0; i < 4; i++) {
        const int r0 = q0 + warpM * 64 + i * 16 + (lane >> 2);
        #pragma unroll
        for (int jj = 0; jj < 8; jj++) {
            const int col = kc0 + warpN * 64 + jj * 8 + (lane & 3) * 2;
            float2 lo = make_float2(acc[i][jj][0], acc[i][jj][1]);
            float2 hi = make_float2(acc[i][jj][2], acc[i][jj][3]);
            *(float2*)(S + (size_t)r0 * NTOK + col)       = lo;
            *(float2*)(S + (size_t)(r0 + 8) * NTOK + col) = hi;
        }
    }

    #pragma unroll
    for (int i = 0; i < 4; i++) {
        float s0 = 0.f, s1 = 0.f;
        #pragma unroll
        for (int jj = 0; jj < 8; jj++) {
            s0 += __expf(acc[i][jj][0] - SHIFTC) + __expf(acc[i][jj][1] - SHIFTC);
            s1 += __expf(acc[i][jj][2] - SHIFTC) + __expf(acc[i][jj][3] - SHIFTC);
        }
        s0 += __shfl_xor_sync(0xffffffffu, s0, 1);
        s0 += __shfl_xor_sync(0xffffffffu, s0, 2);
        s1 += __shfl_xor_sync(0xffffffffu, s1, 1);
        s1 += __shfl_xor_sync(0xffffffffu, s1, 2);
        if ((lane & 3) == 0) {
            int r = warpM * 64 + i * 16 + (lane >> 2);
            zbuf[warpN * 128 + r]     = s0;
            zbuf[warpN * 128 + r + 8] = s1;
        }
    }
    __syncthreads();
    if (tid < 128) {
        float t = zbuf[tid] + zbuf[128 + tid] + zbuf[256 + tid] + zbuf[384 + tid];
        g_Zpart[(blockIdx.y * BATCH + bb) * NTOK + q0 + tid] = t;
    }
}

// ---------------------------------------------------------------------------
// Kernel 3: rZ = 1 / sum_kc Zpart
// ---------------------------------------------------------------------------
__global__ __launch_bounds__(256) void zsum_kernel()
{
    const int i = blockIdx.x * 256 + threadIdx.x;     // 0..32767
    float t = 0.f;
    #pragma unroll
    for (int p = 0; p < 8; p++) t += g_Zpart[p * (BATCH * NTOK) + i];
    g_rZ[i] = 1.0f / t;
}

// ---------------------------------------------------------------------------
// Kernel 4: column-sum partials: c_k partial = sum_q exp(S_qk - C) * rZ_q
// grid (8 kchunks, 16 batch, 8 qchunks)
// ---------------------------------------------------------------------------
__global__ __launch_bounds__(256) void colsum_kernel()
{
    const int bb = blockIdx.y;
    const int qc = blockIdx.z;
    const int k  = blockIdx.x * 256 + threadIdx.x;
    const int qbase = qc * 256;

    __shared__ float shz[256];
    shz[threadIdx.x] = g_rZ[bb * NTOK + qbase + threadIdx.x];
    __syncthreads();

    const float* S = g_S + (size_t)bb * NTOK * NTOK + (size_t)qbase * NTOK + k;
    float acc = 0.f;
    for (int q = 0; q < 256; q += 16) {
        float sv[16];
        #pragma unroll
        for (int u = 0; u < 16; u++) sv[u] = S[(size_t)(q + u) * NTOK];
        #pragma unroll
        for (int u = 0; u < 16; u++)
            acc += __expf(sv[u] - SHIFTC) * shz[q + u];
    }
    g_cpart[(qc * BATCH + bb) * NTOK + k] = acc;
}

// ---------------------------------------------------------------------------
// Kernel 5: ypart[ks][b][d] = sum over 128 k of c[b,k] * x[b,k,d]
// ---------------------------------------------------------------------------
__global__ __launch_bounds__(256) void ypart_kernel(const float* __restrict__ x)
{
    const int bb = blockIdx.y;
    const int ks = blockIdx.x;
    const int k0 = ks * 128;

    __shared__ float sc[128];
    if (threadIdx.x < 128) {
        float s = 0.f;
        #pragma unroll
        for (int p = 0; p < 8; p++)
            s += g_cpart[(p * BATCH + bb) * NTOK + k0 + threadIdx.x];
        sc[threadIdx.x] = s;
    }
    __syncthreads();

    const float* X = x + ((size_t)bb * NTOK + k0) * DDIM + threadIdx.x;
    float acc = 0.f;
    #pragma unroll 8
    for (int kk = 0; kk < 128; kk++)
        acc += sc[kk] * X[(size_t)kk * DDIM];
    g_ypart[(ks * BATCH + bb) * DDIM + threadIdx.x] = acc;
}

// ---------------------------------------------------------------------------
// Kernel 6: out[b,a] = y[b,:] @ W3[:,a] + 2048*b3[a]
// ---------------------------------------------------------------------------
__global__ __launch_bounds__(256) void out_kernel(
    const float* __restrict__ W3, const float* __restrict__ b3,
    float* __restrict__ out)
{
    const int bb = blockIdx.x;
    const int a  = threadIdx.x;

    __shared__ float y[DDIM];
    float t = 0.f;
    #pragma unroll
    for (int p = 0; p < 16; p++) t += g_ypart[(p * BATCH + bb) * DDIM + a];
    y[a] = t;
    __syncthreads();

    float acc = 2048.0f * b3[a];
    #pragma unroll 8
    for (int d = 0; d < DDIM; d++)
        acc += y[d] * W3[(size_t)d * DDIM + a];
    out[bb * DDIM + a] = acc;
}

// ---------------------------------------------------------------------------
extern "C" void kernel_launch(void* const* d_in, const int* in_sizes, int n_in,
                              void* d_out, int out_size)
{
    const float* x  = (const float*)d_in[0];
    const float* W1 = (const float*)d_in[1];
    const float* b1 = (const float*)d_in[2];
    const float* W2 = (const float*)d_in[3];
    const float* b2 = (const float*)d_in[4];
    const float* W3 = (const float*)d_in[5];
    const float* b3 = (const float*)d_in[6];
    float* out = (float*)d_out;

    cudaFuncSetAttribute(score_mma_kernel,
                         cudaFuncAttributeMaxDynamicSharedMemorySize, SC_SMEM);

    proj_kernel<<<dim3(256, 2, 2), 256>>>(x, W1, b1, W2, b2);
    score_mma_kernel<<<dim3(16, 8, 16), 256, SC_SMEM>>>();
    zsum_kernel<<<128, 256>>>();
    colsum_kernel<<<dim3(8, 16, 8), 256>>>();
    ypart_kernel<<<dim3(16, 16), 256>>>(x);
    out_kernel<<<16, 256>>>(W3, b3, out);
}